// round 1
// baseline (speedup 1.0000x reference)
#include <cuda_runtime.h>

#define IMG_H 512
#define IMG_W 512
#define N_PLANES 256          // B*C = 8*32
#define BAND_ROWS 132
#define N_BANDS 4             // 4*132 = 528 >= 512
#define N_ITERS (BAND_ROWS + 8)   // 140, multiple of 10
#define TPB 128               // 128 threads * 4 cols = 512 cols

__device__ double g_acc;

__global__ void sc_init() {
    if (threadIdx.x == 0) g_acc = 0.0;
}

__global__ void sc_final(float* out) {
    if (threadIdx.x == 0) out[0] = (float)(g_acc * 0.125);  // mean over batch of 8
}

__global__ void __launch_bounds__(TPB) sc_main(const float* __restrict__ img) {
    const int tid   = threadIdx.x;
    const int plane = blockIdx.x;
    const int band  = blockIdx.y;
    const int rowStart = band * BAND_ROWS;
    const int c0 = tid << 2;
    const float* base = img + (size_t)plane * (IMG_H * IMG_W);

    const bool left_ok  = (tid > 0);
    const bool right_ok = (tid < TPB - 1);

    // cnt_w per owned column (window-overlap count along W)
    const float cw0 = (float)(min(c0 + 0, 4) + min(IMG_W - 1 - (c0 + 0), 4) + 1);
    const float cw1 = (float)(min(c0 + 1, 4) + min(IMG_W - 1 - (c0 + 1), 4) + 1);
    const float cw2 = (float)(min(c0 + 2, 4) + min(IMG_W - 1 - (c0 + 2), 4) + 1);
    const float cw3 = (float)(min(c0 + 3, 4) + min(IMG_W - 1 - (c0 + 3), 4) + 1);

    float4 hring[10];   // horizontal 9-sums, rows L-9..L
    float4 xring[5];    // raw x, rows L-4..L
#pragma unroll
    for (int i = 0; i < 10; i++) hring[i] = make_float4(0.f, 0.f, 0.f, 0.f);
#pragma unroll
    for (int i = 0; i < 5; i++)  xring[i] = make_float4(0.f, 0.f, 0.f, 0.f);
    float4 S = make_float4(0.f, 0.f, 0.f, 0.f);   // vertical 9-sum of hsum
    float acc = 0.f;

    for (int it = 0; it < N_ITERS / 10; ++it) {
#pragma unroll
        for (int k = 0; k < 10; ++k) {
            const int i = it * 10 + k;
            const int L = rowStart - 4 + i;     // row being loaded

            float4 vL = make_float4(0.f, 0.f, 0.f, 0.f);
            float4 vC = make_float4(0.f, 0.f, 0.f, 0.f);
            float4 vR = make_float4(0.f, 0.f, 0.f, 0.f);
            if (L >= 0 && L < IMG_H) {
                const float4* rp = (const float4*)(base + (size_t)L * IMG_W) + tid;
                if (left_ok)  vL = __ldg(rp - 1);
                vC = __ldg(rp);
                if (right_ok) vR = __ldg(rp + 1);
            }

            // horizontal 9-sums for the 4 owned columns (sliding)
            float s8 = vL.x + vL.y + vL.z + vL.w + vC.x + vC.y + vC.z + vC.w + vR.x;
            float4 hn;
            hn.x = s8;
            hn.y = hn.x - vL.x + vR.y;
            hn.z = hn.y - vL.y + vR.z;
            hn.w = hn.z - vL.z + vR.w;

            // slide vertical sum: S covers hsum rows [L-8, L] after update
            const float4 hold = hring[(k + 1) % 10];   // hsum row L-9
            S.x += hn.x - hold.x;
            S.y += hn.y - hold.y;
            S.z += hn.z - hold.z;
            S.w += hn.w - hold.w;
            hring[k] = hn;

            const float4 xe = xring[(k + 1) % 5];      // x at row r = L-4
            xring[k % 5] = vC;

            // emit row r = L - 4 = rowStart - 8 + i
            const int r = rowStart - 8 + i;
            if (i >= 8 && r < IMG_H) {
                const float cnth = (float)(min(r, 4) + min(IMG_H - 1 - r, 4) + 1);
                float coef, t;
                coef = fmaf(cnth, cw0, 81.0f);
                t = fmaf(coef, xe.x, -2.0f * S.x); acc = fmaf(xe.x, t, acc);
                coef = fmaf(cnth, cw1, 81.0f);
                t = fmaf(coef, xe.y, -2.0f * S.y); acc = fmaf(xe.y, t, acc);
                coef = fmaf(cnth, cw2, 81.0f);
                t = fmaf(coef, xe.z, -2.0f * S.z); acc = fmaf(xe.z, t, acc);
                coef = fmaf(cnth, cw3, 81.0f);
                t = fmaf(coef, xe.w, -2.0f * S.w); acc = fmaf(xe.w, t, acc);
            }
        }
    }

    // block reduction: warp shuffle -> smem -> one double atomic per CTA
    __shared__ float warpsum[TPB / 32];
    float v = acc;
#pragma unroll
    for (int off = 16; off; off >>= 1) v += __shfl_down_sync(0xffffffffu, v, off);
    if ((tid & 31) == 0) warpsum[tid >> 5] = v;
    __syncthreads();
    if (tid == 0) {
        float s = warpsum[0] + warpsum[1] + warpsum[2] + warpsum[3];
        atomicAdd(&g_acc, (double)s);
    }
}

extern "C" void kernel_launch(void* const* d_in, const int* in_sizes, int n_in,
                              void* d_out, int out_size) {
    const float* img = (const float*)d_in[0];
    sc_init<<<1, 32>>>();
    dim3 grid(N_PLANES, N_BANDS);
    sc_main<<<grid, TPB>>>(img);
    sc_final<<<1, 32>>>((float*)d_out);
}

// round 2
// speedup vs baseline: 2.0844x; 2.0844x over previous
#include <cuda_runtime.h>

#define IMG_H 512
#define IMG_W 512
#define N_PLANES 256          // B*C = 8*32
#define BAND_ROWS 132
#define N_BANDS 4             // 4*132 = 528 >= 512
#define N_ITERS (BAND_ROWS + 8)   // 140, multiple of 10
#define TPB 128               // 128 threads * 4 cols = 512 cols

__device__ double g_acc;

__global__ void sc_init() {
    if (threadIdx.x == 0) g_acc = 0.0;
}

__global__ void sc_final(float* out) {
    if (threadIdx.x == 0) out[0] = (float)(g_acc * 0.125);  // mean over batch of 8
}

// Load one padded row: unconditional clamped loads + mask multiply.
// mL/mR fold in the thread-edge halo zeroing; m is the row-validity mask.
__device__ __forceinline__ void load_row(
    const float* __restrict__ base, int L, int tid,
    int dL, int dR, float mLc, float mRc,
    float4& vL, float4& vC, float4& vR)
{
    int Lc = min(max(L, 0), IMG_H - 1);
    float m = (L >= 0 && L < IMG_H) ? 1.0f : 0.0f;
    const float4* rp = (const float4*)(base + (size_t)Lc * IMG_W) + tid;
    float4 a = __ldg(rp + dL);   // dL = -1 normally, 0 at left edge
    float4 b = __ldg(rp);
    float4 c = __ldg(rp + dR);   // dR = +1 normally, 0 at right edge
    float mL = m * mLc, mR = m * mRc;
    vL = make_float4(a.x * mL, a.y * mL, a.z * mL, a.w * mL);
    vC = make_float4(b.x * m,  b.y * m,  b.z * m,  b.w * m);
    vR = make_float4(c.x * mR, c.y * mR, c.z * mR, c.w * mR);
}

__global__ void __launch_bounds__(TPB, 7) sc_main(const float* __restrict__ img) {
    const int tid   = threadIdx.x;
    const int plane = blockIdx.x;
    const int band  = blockIdx.y;
    const int rowStart = band * BAND_ROWS;
    const int c0 = tid << 2;
    const float* base = img + (size_t)plane * (IMG_H * IMG_W);

    const int  dL  = (tid > 0) ? -1 : 0;
    const int  dR  = (tid < TPB - 1) ? 1 : 0;
    const float mLc = (tid > 0) ? 1.0f : 0.0f;
    const float mRc = (tid < TPB - 1) ? 1.0f : 0.0f;

    // cnt_w per owned column (window-overlap count along W)
    const float cw0 = (float)(min(c0 + 0, 4) + min(IMG_W - 1 - (c0 + 0), 4) + 1);
    const float cw1 = (float)(min(c0 + 1, 4) + min(IMG_W - 1 - (c0 + 1), 4) + 1);
    const float cw2 = (float)(min(c0 + 2, 4) + min(IMG_W - 1 - (c0 + 2), 4) + 1);
    const float cw3 = (float)(min(c0 + 3, 4) + min(IMG_W - 1 - (c0 + 3), 4) + 1);

    // horizontal-9-sum ring lives in SMEM (private slot per thread, no barriers)
    __shared__ float4 hs[10][TPB];
#pragma unroll
    for (int i = 0; i < 10; i++) hs[i][tid] = make_float4(0.f, 0.f, 0.f, 0.f);

    float4 xring[5];    // raw x, rows L-4..L (registers)
#pragma unroll
    for (int i = 0; i < 5; i++)  xring[i] = make_float4(0.f, 0.f, 0.f, 0.f);
    float4 S = make_float4(0.f, 0.f, 0.f, 0.f);   // vertical 9-sum of hsum
    float acc = 0.f;

    // software pipeline: prefetch row i=0
    float4 cvL, cvC, cvR;
    load_row(base, rowStart - 4, tid, dL, dR, mLc, mRc, cvL, cvC, cvR);

    for (int it = 0; it < N_ITERS / 10; ++it) {
#pragma unroll
        for (int k = 0; k < 10; ++k) {
            const int i = it * 10 + k;

            // prefetch row i+1 (unconditional, clamped) BEFORE consuming row i
            float4 nvL, nvC, nvR;
            load_row(base, rowStart - 4 + i + 1, tid, dL, dR, mLc, mRc, nvL, nvC, nvR);

            // horizontal 9-sums for the 4 owned columns (sliding)
            float s8 = cvL.x + cvL.y + cvL.z + cvL.w
                     + cvC.x + cvC.y + cvC.z + cvC.w + cvR.x;
            float4 hn;
            hn.x = s8;
            hn.y = hn.x - cvL.x + cvR.y;
            hn.z = hn.y - cvL.y + cvR.z;
            hn.w = hn.z - cvL.z + cvR.w;

            // slide vertical sum: S covers hsum rows [L-8, L] after update
            const float4 hold = hs[(k + 1) % 10][tid];   // hsum row L-9
            S.x += hn.x - hold.x;
            S.y += hn.y - hold.y;
            S.z += hn.z - hold.z;
            S.w += hn.w - hold.w;
            hs[k][tid] = hn;

            const float4 xe = xring[(k + 1) % 5];        // x at row r = L-4
            xring[k % 5] = cvC;

            // advance pipeline
            cvL = nvL; cvC = nvC; cvR = nvR;

            // emit row r = L - 4 = rowStart - 8 + i
            const int r = rowStart - 8 + i;
            if (i >= 8 && r < IMG_H) {
                const float cnth = (float)(min(r, 4) + min(IMG_H - 1 - r, 4) + 1);
                float coef, t;
                coef = fmaf(cnth, cw0, 81.0f);
                t = fmaf(coef, xe.x, -2.0f * S.x); acc = fmaf(xe.x, t, acc);
                coef = fmaf(cnth, cw1, 81.0f);
                t = fmaf(coef, xe.y, -2.0f * S.y); acc = fmaf(xe.y, t, acc);
                coef = fmaf(cnth, cw2, 81.0f);
                t = fmaf(coef, xe.z, -2.0f * S.z); acc = fmaf(xe.z, t, acc);
                coef = fmaf(cnth, cw3, 81.0f);
                t = fmaf(coef, xe.w, -2.0f * S.w); acc = fmaf(xe.w, t, acc);
            }
        }
    }

    // block reduction: warp shuffle -> smem -> one double atomic per CTA
    __shared__ float warpsum[TPB / 32];
    float v = acc;
#pragma unroll
    for (int off = 16; off; off >>= 1) v += __shfl_down_sync(0xffffffffu, v, off);
    if ((tid & 31) == 0) warpsum[tid >> 5] = v;
    __syncthreads();
    if (tid == 0) {
        float s = warpsum[0] + warpsum[1] + warpsum[2] + warpsum[3];
        atomicAdd(&g_acc, (double)s);
    }
}

extern "C" void kernel_launch(void* const* d_in, const int* in_sizes, int n_in,
                              void* d_out, int out_size) {
    const float* img = (const float*)d_in[0];
    sc_init<<<1, 32>>>();
    dim3 grid(N_PLANES, N_BANDS);
    sc_main<<<grid, TPB>>>(img);
    sc_final<<<1, 32>>>((float*)d_out);
}